// round 14
// baseline (speedup 1.0000x reference)
#include <cuda_runtime.h>
#include <cuda_bf16.h>
#include <cstdint>

// ConeProjection: out[b,k] = P[k]^T * sigma[b] * P[k]
//   sigma[a][c] = (vn·w_a)(vn·w_c) - alpha*(w_a·w_c)
//   w0 = R[:,0], w1 = R[:,1], w2 = t - eyes, vn = v/max(||v||,1e-14)
//   P[k] = ((ki-6)/6, (kj-6)/6, 1),  k = 13*ki + kj
//
// R12 FFMA2 compute + TMA bulk stores: each warp computes 4-batch chunks
// (676 floats = 2704 B) into a double-buffered smem stage with cheap
// conflict-free STS.32, then ONE lane issues cp.async.bulk (smem -> gmem,
// bulk_group). This deletes ~94 STG.32 x 5-cycle issue slots per warp and
// all L1 global-store wavefronts; output flows smem -> TMA -> L2.

#define K_GRID   169
#define NB       16            // batches per warp
#define WARPS    8             // warps per block
#define THREADS  (WARPS * 32)
#define CHUNK    4             // batches per TMA chunk
#define NCHUNK   (NB / CHUNK)  // 4
#define CHUNK_F  (CHUNK * K_GRID)   // 676 floats = 2704 B (16B multiple)

__device__ __forceinline__ unsigned long long pack2f(float lo, float hi) {
    unsigned long long d;
    asm("mov.b64 %0, {%1, %2};" : "=l"(d) : "f"(lo), "f"(hi));
    return d;
}
__device__ __forceinline__ unsigned long long fma2(unsigned long long a,
                                                   unsigned long long b,
                                                   unsigned long long c) {
    unsigned long long d;
    asm("fma.rn.f32x2 %0, %1, %2, %3;" : "=l"(d) : "l"(a), "l"(b), "l"(c));
    return d;
}
__device__ __forceinline__ void unpack2f(unsigned long long s, float& lo, float& hi) {
    asm("mov.b64 {%0, %1}, %2;" : "=f"(lo), "=f"(hi) : "l"(s));
}

__global__ __launch_bounds__(THREADS)
void cone_projection_kernel(const float* __restrict__ eyes,
                            const float* __restrict__ v,
                            const float* __restrict__ R,
                            const float* __restrict__ t,
                            const float* __restrict__ alpha,
                            float* __restrict__ out,
                            int B)
{
    // per batch: (c0,c1,c2,c3) , (c4,c5,-,-)   -> 32 B/batch, 4 KB total
    __shared__ float4 scoef[WARPS * NB * 2];
    // per warp: double-buffered 4-batch stage, 2 x 2704 B x 8 warps = 43.3 KB
    __shared__ float stage[WARPS][2][CHUNK_F];

    const int lane = threadIdx.x & 31;
    const int wid  = threadIdx.x >> 5;
    const long long base_b = ((long long)blockIdx.x * WARPS + wid) * NB;

    // --- Packed per-thread coords for pass-pair pp: elements
    //     k0 = lane + 64*pp (lo), k1 = k0 + 32 (hi); pp = 0..2 ---
    unsigned long long X[3], Y[3];
    #pragma unroll
    for (int pp = 0; pp < 3; ++pp) {
        float xv[2], yv[2];
        #pragma unroll
        for (int h = 0; h < 2; ++h) {
            const int k  = lane + 64 * pp + 32 * h;   // k1 may exceed 168: predicated off
            const int ki = (k * 79) >> 10;            // k/13, exact for k < 169
            const int kj = k - 13 * ki;
            xv[h] = (float)(ki - 6) * (1.0f / 6.0f);
            yv[h] = (float)(kj - 6) * (1.0f / 6.0f);
        }
        X[pp] = pack2f(xv[0], xv[1]);
        Y[pp] = pack2f(yv[0], yv[1]);
    }

    // --- Phase A: lanes 0..15 build coefficients for their batch ---
    if (lane < NB) {
        const long long b = base_b + lane;
        if (b < B) {
            float vx = v[b * 3 + 0];
            float vy = v[b * 3 + 1];
            float vz = v[b * 3 + 2];
            float n  = fmaxf(sqrtf(vx * vx + vy * vy + vz * vz), 1e-14f);
            float inv = 1.0f / n;
            vx *= inv; vy *= inv; vz *= inv;

            const float a = alpha[b];

            const float* Rb = R + b * 9;
            const float w0x = Rb[0], w0y = Rb[3], w0z = Rb[6];   // R[:,0]
            const float w1x = Rb[1], w1y = Rb[4], w1z = Rb[7];   // R[:,1]
            const float w2x = t[b * 3 + 0] - eyes[b * 3 + 0];
            const float w2y = t[b * 3 + 1] - eyes[b * 3 + 1];
            const float w2z = t[b * 3 + 2] - eyes[b * 3 + 2];

            const float d0 = vx * w0x + vy * w0y + vz * w0z;
            const float d1 = vx * w1x + vy * w1y + vz * w1z;
            const float d2 = vx * w2x + vy * w2y + vz * w2z;

            const float c0 = d0 * d0 - a * (w0x * w0x + w0y * w0y + w0z * w0z); // x^2
            const float c1 = d1 * d1 - a * (w1x * w1x + w1y * w1y + w1z * w1z); // y^2
            const float c2 = d2 * d2 - a * (w2x * w2x + w2y * w2y + w2z * w2z); // 1
            const float c3 = 2.0f * (d0 * d1 - a * (w0x * w1x + w0y * w1y + w0z * w1z)); // xy
            const float c4 = 2.0f * (d0 * d2 - a * (w0x * w2x + w0y * w2y + w0z * w2z)); // x
            const float c5 = 2.0f * (d1 * d2 - a * (w1x * w2x + w1y * w2y + w1z * w2z)); // y

            const int s = (wid * NB + lane) * 2;
            scoef[s]     = make_float4(c0, c1, c2, c3);
            scoef[s + 1] = make_float4(c4, c5, 0.0f, 0.0f);
        }
    }
    __syncwarp();

    const bool full_group = (base_b + NB <= B);

    if (full_group) {
        // --- Phase B: 4 chunks of 4 batches; compute -> smem stage -> TMA bulk ---
        for (int c = 0; c < NCHUNK; ++c) {
            const int buf = c & 1;

            // before reusing this buffer, ensure its previous TMA read finished
            if (c >= 2 && lane == 0)
                asm volatile("cp.async.bulk.wait_group 1;" ::: "memory");
            __syncwarp();

            float* stg = &stage[wid][buf][0];

            #pragma unroll
            for (int lb = 0; lb < CHUNK; ++lb) {
                const int bt = c * CHUNK + lb;
                const int s  = (wid * NB + bt) * 2;
                const float4 ca = scoef[s];       // c0 c1 c2 c3
                const float4 cb = scoef[s + 1];   // c4 c5 -  -

                const unsigned long long Q0 = pack2f(ca.x, ca.x);  // c0
                const unsigned long long Q1 = pack2f(ca.y, ca.y);  // c1
                const unsigned long long Q2 = pack2f(ca.z, ca.z);  // c2
                const unsigned long long Q3 = pack2f(ca.w, ca.w);  // c3
                const unsigned long long Q4 = pack2f(cb.x, cb.x);  // c4
                const unsigned long long Q5 = pack2f(cb.y, cb.y);  // c5

                float* dst = stg + lb * K_GRID + lane;

                #pragma unroll
                for (int pp = 0; pp < 3; ++pp) {
                    // r = x*(c0*x + c4) + (y*(c1*y + c3*x + c5) + c2)
                    unsigned long long u = fma2(Q0, X[pp], Q4);
                    unsigned long long w = fma2(Q3, X[pp], Q5);
                    w = fma2(Q1, Y[pp], w);
                    unsigned long long sa = fma2(Y[pp], w, Q2);
                    unsigned long long r  = fma2(X[pp], u, sa);
                    float rlo, rhi;
                    unpack2f(r, rlo, rhi);
                    dst[64 * pp] = rlo;                          // STS.32, conflict-free
                    if (pp < 2 || lane < K_GRID - 160)           // k = 160+lane < 169
                        dst[64 * pp + 32] = rhi;
                }
            }
            __syncwarp();

            if (lane == 0) {
                asm volatile("fence.proxy.async.shared::cta;" ::: "memory");
                const unsigned long long gdst =
                    (unsigned long long)(out + (base_b + (long long)c * CHUNK) * K_GRID);
                const unsigned ssrc = (unsigned)__cvta_generic_to_shared(stg);
                asm volatile(
                    "cp.async.bulk.global.shared::cta.bulk_group [%0], [%1], %2;"
                    :: "l"(gdst), "r"(ssrc), "r"(CHUNK_F * 4) : "memory");
                asm volatile("cp.async.bulk.commit_group;" ::: "memory");
            }
        }
        if (lane == 0)
            asm volatile("cp.async.bulk.wait_group 0;" ::: "memory");
        __syncwarp();
    } else {
        // --- Tail fallback (B not multiple of NB): direct guarded stores ---
        for (int bt = 0; bt < NB; ++bt) {
            const long long b = base_b + bt;
            if (b >= B) break;
            const int s = (wid * NB + bt) * 2;
            const float4 ca = scoef[s];
            const float4 cb = scoef[s + 1];
            const unsigned long long Q0 = pack2f(ca.x, ca.x);
            const unsigned long long Q1 = pack2f(ca.y, ca.y);
            const unsigned long long Q2 = pack2f(ca.z, ca.z);
            const unsigned long long Q3 = pack2f(ca.w, ca.w);
            const unsigned long long Q4 = pack2f(cb.x, cb.x);
            const unsigned long long Q5 = pack2f(cb.y, cb.y);
            float* o = out + b * (long long)K_GRID + lane;
            #pragma unroll
            for (int pp = 0; pp < 3; ++pp) {
                unsigned long long u = fma2(Q0, X[pp], Q4);
                unsigned long long w = fma2(Q3, X[pp], Q5);
                w = fma2(Q1, Y[pp], w);
                unsigned long long sa = fma2(Y[pp], w, Q2);
                unsigned long long r  = fma2(X[pp], u, sa);
                float rlo, rhi;
                unpack2f(r, rlo, rhi);
                __stcs(&o[64 * pp], rlo);
                if (pp < 2 || lane < K_GRID - 160)
                    __stcs(&o[64 * pp + 32], rhi);
            }
        }
    }
}

extern "C" void kernel_launch(void* const* d_in, const int* in_sizes, int n_in,
                              void* d_out, int out_size) {
    const float* eyes  = (const float*)d_in[0];
    const float* v     = (const float*)d_in[1];
    const float* R     = (const float*)d_in[2];
    const float* t     = (const float*)d_in[3];
    const float* alpha = (const float*)d_in[4];
    float* out = (float*)d_out;

    const int B = in_sizes[4];                            // alpha: B elements
    const int warp_groups = (B + NB - 1) / NB;            // 8192 for B=131072
    const int blocks = (warp_groups + WARPS - 1) / WARPS; // 1024

    cone_projection_kernel<<<blocks, THREADS>>>(eyes, v, R, t, alpha, out, B);
}

// round 15
// speedup vs baseline: 1.0718x; 1.0718x over previous
#include <cuda_runtime.h>
#include <cuda_bf16.h>

// ConeProjection: out[b,k] = P[k]^T * sigma[b] * P[k]
//   sigma[a][c] = (vn·w_a)(vn·w_c) - alpha*(w_a·w_c)
//   w0 = R[:,0], w1 = R[:,1], w2 = t - eyes, vn = v/max(||v||,1e-14)
//   P[k] = ((ki-6)/6, (kj-6)/6, 1),  k = 13*ki + kj
//
// R12 structure (best measured): warp owns 16 batches; lanes 0..15 build the
// 6 quadratic coefficients, stored PRE-DUPLICATED as (c,c) pairs in smem;
// phase B evaluates pass-pairs with packed fma.rn.f32x2 (5 FFMA2 per 64
// elements) and coalesced streaming STG.32. 44 regs -> 5 blocks/SM.
// NEW vs R12: all input loads use __ldcs (evict-first). Steady-state wall
// time is DRAM-drain bound (~98.6 MB/iter); read-once inputs must not
// occupy L2 capacity needed to buffer the 88.6 MB dirty output stream.

#define K_GRID  169
#define NB      16            // batches per warp
#define WARPS   8             // warps per block
#define THREADS (WARPS * 32)

__device__ __forceinline__ unsigned long long pack2f(float lo, float hi) {
    unsigned long long d;
    asm("mov.b64 %0, {%1, %2};" : "=l"(d) : "f"(lo), "f"(hi));
    return d;
}
__device__ __forceinline__ unsigned long long fma2(unsigned long long a,
                                                   unsigned long long b,
                                                   unsigned long long c) {
    unsigned long long d;
    asm("fma.rn.f32x2 %0, %1, %2, %3;" : "=l"(d) : "l"(a), "l"(b), "l"(c));
    return d;
}
__device__ __forceinline__ void unpack2f(unsigned long long s, float& lo, float& hi) {
    asm("mov.b64 {%0, %1}, %2;" : "=f"(lo), "=f"(hi) : "l"(s));
}

__global__ __launch_bounds__(THREADS, 5)
void cone_projection_kernel(const float* __restrict__ eyes,
                            const float* __restrict__ v,
                            const float* __restrict__ R,
                            const float* __restrict__ t,
                            const float* __restrict__ alpha,
                            float* __restrict__ out,
                            int B)
{
    // per batch, 3 float4: (c0,c0,c1,c1), (c3,c3,c4,c4), (c5,c5,c2,c2)
    __shared__ float4 scoef[WARPS * NB * 3];

    const int lane = threadIdx.x & 31;
    const int wid  = threadIdx.x >> 5;
    const long long base_b = ((long long)blockIdx.x * WARPS + wid) * NB;

    // --- Packed per-thread coords for pass-pair pp: elements
    //     k0 = lane + 64*pp (lo), k1 = k0 + 32 (hi); pp = 0..2 (12 regs) ---
    unsigned long long X[3], Y[3];
    #pragma unroll
    for (int pp = 0; pp < 3; ++pp) {
        float xv[2], yv[2];
        #pragma unroll
        for (int h = 0; h < 2; ++h) {
            const int k  = lane + 64 * pp + 32 * h;   // k1 may exceed 168: store predicated off
            const int ki = (k * 79) >> 10;            // k/13, exact for k < 169
            const int kj = k - 13 * ki;
            xv[h] = (float)(ki - 6) * (1.0f / 6.0f);
            yv[h] = (float)(kj - 6) * (1.0f / 6.0f);
        }
        X[pp] = pack2f(xv[0], xv[1]);
        Y[pp] = pack2f(yv[0], yv[1]);
    }

    // --- Phase A: lanes 0..15 build duplicated coefficient pairs ---
    // All input loads evict-first (__ldcs): read-once data, keep L2 for the
    // output write-buffer working set.
    if (lane < NB) {
        const long long b = base_b + lane;
        if (b < B) {
            float vx = __ldcs(&v[b * 3 + 0]);
            float vy = __ldcs(&v[b * 3 + 1]);
            float vz = __ldcs(&v[b * 3 + 2]);
            float n  = fmaxf(sqrtf(vx * vx + vy * vy + vz * vz), 1e-14f);
            float inv = 1.0f / n;
            vx *= inv; vy *= inv; vz *= inv;

            const float a = __ldcs(&alpha[b]);

            const float* Rb = R + b * 9;
            const float w0x = __ldcs(&Rb[0]), w0y = __ldcs(&Rb[3]), w0z = __ldcs(&Rb[6]); // R[:,0]
            const float w1x = __ldcs(&Rb[1]), w1y = __ldcs(&Rb[4]), w1z = __ldcs(&Rb[7]); // R[:,1]
            const float w2x = __ldcs(&t[b * 3 + 0]) - __ldcs(&eyes[b * 3 + 0]);
            const float w2y = __ldcs(&t[b * 3 + 1]) - __ldcs(&eyes[b * 3 + 1]);
            const float w2z = __ldcs(&t[b * 3 + 2]) - __ldcs(&eyes[b * 3 + 2]);

            const float d0 = vx * w0x + vy * w0y + vz * w0z;
            const float d1 = vx * w1x + vy * w1y + vz * w1z;
            const float d2 = vx * w2x + vy * w2y + vz * w2z;

            const float c0 = d0 * d0 - a * (w0x * w0x + w0y * w0y + w0z * w0z); // x^2
            const float c1 = d1 * d1 - a * (w1x * w1x + w1y * w1y + w1z * w1z); // y^2
            const float c2 = d2 * d2 - a * (w2x * w2x + w2y * w2y + w2z * w2z); // 1
            const float c3 = 2.0f * (d0 * d1 - a * (w0x * w1x + w0y * w1y + w0z * w1z)); // xy
            const float c4 = 2.0f * (d0 * d2 - a * (w0x * w2x + w0y * w2y + w0z * w2z)); // x
            const float c5 = 2.0f * (d1 * d2 - a * (w1x * w2x + w1y * w2y + w1z * w2z)); // y

            const int s = (wid * NB + lane) * 3;
            scoef[s]     = make_float4(c0, c0, c1, c1);
            scoef[s + 1] = make_float4(c3, c3, c4, c4);
            scoef[s + 2] = make_float4(c5, c5, c2, c2);
        }
    }
    __syncwarp();

    // --- Phase B: 16 batches x (3 broadcast LDS.128 + 3 x (5 FFMA2 + 2 STG)) ---
    const ulonglong2* sc2 = reinterpret_cast<const ulonglong2*>(scoef);

    #pragma unroll 4
    for (int bt = 0; bt < NB; ++bt) {
        const long long b = base_b + bt;
        if (b >= B) break;

        const int s = (wid * NB + bt) * 3;
        const ulonglong2 q0 = sc2[s];       // (c0,c0) , (c1,c1)
        const ulonglong2 q1 = sc2[s + 1];   // (c3,c3) , (c4,c4)
        const ulonglong2 q2 = sc2[s + 2];   // (c5,c5) , (c2,c2)

        float* o = out + b * (long long)K_GRID + lane;

        #pragma unroll
        for (int pp = 0; pp < 3; ++pp) {
            // r = x*(c0*x + c4) + (y*(c1*y + c3*x + c5) + c2), packed f32x2
            unsigned long long u = fma2(q0.x, X[pp], q1.y);   // c0*x + c4
            unsigned long long w = fma2(q1.x, X[pp], q2.x);   // c3*x + c5
            w = fma2(q0.y, Y[pp], w);                         // + c1*y
            unsigned long long sacc = fma2(Y[pp], w, q2.y);   // y*w + c2
            unsigned long long r = fma2(X[pp], u, sacc);      // + x*u
            float rlo, rhi;
            unpack2f(r, rlo, rhi);
            __stcs(&o[64 * pp], rlo);                 // pass 2*pp   (always valid)
            if (pp < 2 || lane < K_GRID - 160)        // pass 5: k = 160+lane < 169
                __stcs(&o[64 * pp + 32], rhi);        // pass 2*pp+1
        }
    }
}

extern "C" void kernel_launch(void* const* d_in, const int* in_sizes, int n_in,
                              void* d_out, int out_size) {
    const float* eyes  = (const float*)d_in[0];
    const float* v     = (const float*)d_in[1];
    const float* R     = (const float*)d_in[2];
    const float* t     = (const float*)d_in[3];
    const float* alpha = (const float*)d_in[4];
    float* out = (float*)d_out;

    const int B = in_sizes[4];                            // alpha: B elements
    const int warp_groups = (B + NB - 1) / NB;            // 8192 for B=131072
    const int blocks = (warp_groups + WARPS - 1) / WARPS; // 1024

    cone_projection_kernel<<<blocks, THREADS>>>(eyes, v, R, t, alpha, out, B);
}

// round 16
// speedup vs baseline: 1.0736x; 1.0017x over previous
#include <cuda_runtime.h>
#include <cuda_bf16.h>

// ConeProjection: out[b,k] = P[k]^T * sigma[b] * P[k]
//   sigma[a][c] = (vn·w_a)(vn·w_c) - alpha*(w_a·w_c)
//   w0 = R[:,0], w1 = R[:,1], w2 = t - eyes, vn = v/max(||v||,1e-14)
//   P[k] = ((ki-6)/6, (kj-6)/6, 1),  k = 13*ki + kj
//
// Converged structure (R12 base, best measured kernel dur): warp owns 16
// batches; lanes 0..15 build the 6 quadratic coefficients, stored
// PRE-DUPLICATED as (c,c) f32x2 pairs in smem; phase B evaluates element
// pass-pairs with packed fma.rn.f32x2 and coalesced evict-first STG.32.
// R15 micro-wins: depth-3 FFMA2 tree (was depth-4) and hoisted batch-bound
// guard (grid covers B exactly; guarded tail kept for generality).

#define K_GRID  169
#define NB      16            // batches per warp
#define WARPS   8             // warps per block
#define THREADS (WARPS * 32)

__device__ __forceinline__ unsigned long long pack2f(float lo, float hi) {
    unsigned long long d;
    asm("mov.b64 %0, {%1, %2};" : "=l"(d) : "f"(lo), "f"(hi));
    return d;
}
__device__ __forceinline__ unsigned long long fma2(unsigned long long a,
                                                   unsigned long long b,
                                                   unsigned long long c) {
    unsigned long long d;
    asm("fma.rn.f32x2 %0, %1, %2, %3;" : "=l"(d) : "l"(a), "l"(b), "l"(c));
    return d;
}
__device__ __forceinline__ void unpack2f(unsigned long long s, float& lo, float& hi) {
    asm("mov.b64 {%0, %1}, %2;" : "=f"(lo), "=f"(hi) : "l"(s));
}

__global__ __launch_bounds__(THREADS, 5)
void cone_projection_kernel(const float* __restrict__ eyes,
                            const float* __restrict__ v,
                            const float* __restrict__ R,
                            const float* __restrict__ t,
                            const float* __restrict__ alpha,
                            float* __restrict__ out,
                            int B)
{
    // per batch, 3 float4: (c0,c0,c1,c1), (c3,c3,c4,c4), (c5,c5,c2,c2)
    __shared__ float4 scoef[WARPS * NB * 3];

    const int lane = threadIdx.x & 31;
    const int wid  = threadIdx.x >> 5;
    const long long base_b = ((long long)blockIdx.x * WARPS + wid) * NB;

    // --- Packed per-thread coords for pass-pair pp: elements
    //     k0 = lane + 64*pp (lo), k1 = k0 + 32 (hi); pp = 0..2 (12 regs) ---
    unsigned long long X[3], Y[3];
    #pragma unroll
    for (int pp = 0; pp < 3; ++pp) {
        float xv[2], yv[2];
        #pragma unroll
        for (int h = 0; h < 2; ++h) {
            const int k  = lane + 64 * pp + 32 * h;   // k1 may exceed 168: store predicated off
            const int ki = (k * 79) >> 10;            // k/13, exact for k < 169
            const int kj = k - 13 * ki;
            xv[h] = (float)(ki - 6) * (1.0f / 6.0f);
            yv[h] = (float)(kj - 6) * (1.0f / 6.0f);
        }
        X[pp] = pack2f(xv[0], xv[1]);
        Y[pp] = pack2f(yv[0], yv[1]);
    }

    // --- Phase A: lanes 0..15 build duplicated coefficient pairs ---
    if (lane < NB) {
        const long long b = base_b + lane;
        if (b < B) {
            float vx = v[b * 3 + 0];
            float vy = v[b * 3 + 1];
            float vz = v[b * 3 + 2];
            float n  = fmaxf(sqrtf(vx * vx + vy * vy + vz * vz), 1e-14f);
            float inv = 1.0f / n;
            vx *= inv; vy *= inv; vz *= inv;

            const float a = alpha[b];

            const float* Rb = R + b * 9;
            const float w0x = Rb[0], w0y = Rb[3], w0z = Rb[6];   // R[:,0]
            const float w1x = Rb[1], w1y = Rb[4], w1z = Rb[7];   // R[:,1]
            const float w2x = t[b * 3 + 0] - eyes[b * 3 + 0];
            const float w2y = t[b * 3 + 1] - eyes[b * 3 + 1];
            const float w2z = t[b * 3 + 2] - eyes[b * 3 + 2];

            const float d0 = vx * w0x + vy * w0y + vz * w0z;
            const float d1 = vx * w1x + vy * w1y + vz * w1z;
            const float d2 = vx * w2x + vy * w2y + vz * w2z;

            const float c0 = d0 * d0 - a * (w0x * w0x + w0y * w0y + w0z * w0z); // x^2
            const float c1 = d1 * d1 - a * (w1x * w1x + w1y * w1y + w1z * w1z); // y^2
            const float c2 = d2 * d2 - a * (w2x * w2x + w2y * w2y + w2z * w2z); // 1
            const float c3 = 2.0f * (d0 * d1 - a * (w0x * w1x + w0y * w1y + w0z * w1z)); // xy
            const float c4 = 2.0f * (d0 * d2 - a * (w0x * w2x + w0y * w2y + w0z * w2z)); // x
            const float c5 = 2.0f * (d1 * d2 - a * (w1x * w2x + w1y * w2y + w1z * w2z)); // y

            const int s = (wid * NB + lane) * 3;
            scoef[s]     = make_float4(c0, c0, c1, c1);
            scoef[s + 1] = make_float4(c3, c3, c4, c4);
            scoef[s + 2] = make_float4(c5, c5, c2, c2);
        }
    }
    __syncwarp();

    // --- Phase B: 16 batches x (3 broadcast LDS.128 + 3 x (5 FFMA2 + 2 STG)) ---
    const ulonglong2* sc2 = reinterpret_cast<const ulonglong2*>(scoef);
    const bool full_group = (base_b + NB <= B);

    if (full_group) {
        #pragma unroll 4
        for (int bt = 0; bt < NB; ++bt) {
            const long long b = base_b + bt;

            const int s = (wid * NB + bt) * 3;
            const ulonglong2 q0 = sc2[s];       // (c0,c0) , (c1,c1)
            const ulonglong2 q1 = sc2[s + 1];   // (c3,c3) , (c4,c4)
            const ulonglong2 q2 = sc2[s + 2];   // (c5,c5) , (c2,c2)

            float* o = out + b * (long long)K_GRID + lane;

            #pragma unroll
            for (int pp = 0; pp < 3; ++pp) {
                // depth-3 tree:
                //   a1 = c0*x + c4 ; a2 = c1*y + c5            (parallel)
                //   b1 = a1 + c3*y ; s1 = y*a2 + c2            (parallel)
                //   r  = x*b1 + s1
                unsigned long long a1 = fma2(q0.x, X[pp], q1.y);
                unsigned long long a2 = fma2(q0.y, Y[pp], q2.x);
                unsigned long long b1 = fma2(q1.x, Y[pp], a1);
                unsigned long long s1 = fma2(Y[pp], a2, q2.y);
                unsigned long long r  = fma2(X[pp], b1, s1);
                float rlo, rhi;
                unpack2f(r, rlo, rhi);
                __stcs(&o[64 * pp], rlo);                 // pass 2*pp (always valid)
                if (pp < 2 || lane < K_GRID - 160)        // pass 5: k = 160+lane < 169
                    __stcs(&o[64 * pp + 32], rhi);        // pass 2*pp+1
            }
        }
    } else {
        // --- Guarded tail (B not a multiple of NB) ---
        for (int bt = 0; bt < NB; ++bt) {
            const long long b = base_b + bt;
            if (b >= B) break;

            const int s = (wid * NB + bt) * 3;
            const ulonglong2 q0 = sc2[s];
            const ulonglong2 q1 = sc2[s + 1];
            const ulonglong2 q2 = sc2[s + 2];

            float* o = out + b * (long long)K_GRID + lane;

            #pragma unroll
            for (int pp = 0; pp < 3; ++pp) {
                unsigned long long a1 = fma2(q0.x, X[pp], q1.y);
                unsigned long long a2 = fma2(q0.y, Y[pp], q2.x);
                unsigned long long b1 = fma2(q1.x, Y[pp], a1);
                unsigned long long s1 = fma2(Y[pp], a2, q2.y);
                unsigned long long r  = fma2(X[pp], b1, s1);
                float rlo, rhi;
                unpack2f(r, rlo, rhi);
                __stcs(&o[64 * pp], rlo);
                if (pp < 2 || lane < K_GRID - 160)
                    __stcs(&o[64 * pp + 32], rhi);
            }
        }
    }
}

extern "C" void kernel_launch(void* const* d_in, const int* in_sizes, int n_in,
                              void* d_out, int out_size) {
    const float* eyes  = (const float*)d_in[0];
    const float* v     = (const float*)d_in[1];
    const float* R     = (const float*)d_in[2];
    const float* t     = (const float*)d_in[3];
    const float* alpha = (const float*)d_in[4];
    float* out = (float*)d_out;

    const int B = in_sizes[4];                            // alpha: B elements
    const int warp_groups = (B + NB - 1) / NB;            // 8192 for B=131072
    const int blocks = (warp_groups + WARPS - 1) / WARPS; // 1024

    cone_projection_kernel<<<blocks, THREADS>>>(eyes, v, R, t, alpha, out, B);
}